// round 3
// baseline (speedup 1.0000x reference)
#include <cuda_runtime.h>
#include <cuda_bf16.h>

// HungarianMatcher cost matrix, diagonal only.
// Inputs (metadata order):
//   d_in[0] pred_logits   f32 (64, 300, 200)
//   d_in[1] pred_segments f32 (64, 300, 2)   (center, width)
//   d_in[2] tgt_segments  f32 (64, 32, 2)
//   d_in[3] lengths       f32 (64, 1)
//   d_in[4] tgt_labels    int (64, 32)  -- declared int64, but JAX w/o x64
//                                          emits int32; detected at runtime.
// Output: f32 (64, 300, 32):
//   out[b,q,t] = |cq-ct|+|wq-wt| - softmax(logits[b,q])[label_t] - gIoU(scaled)

#define BS 64
#define NQ 300
#define NC 200
#define NT 32
#define WARPS_PER_BLOCK 8
#define NC4 (NC / 4)   // 50 float4 per row

__global__ __launch_bounds__(WARPS_PER_BLOCK * 32)
void matcher_kernel(const float* __restrict__ logits,
                    const float* __restrict__ pred_seg,
                    const float* __restrict__ tgt_seg,
                    const float* __restrict__ lengths,
                    const int*   __restrict__ labels32,   // raw label buffer
                    float* __restrict__ out)
{
    const int b    = blockIdx.y;
    const int warp = threadIdx.x >> 5;
    const int lane = threadIdx.x & 31;
    const int q    = blockIdx.x * WARPS_PER_BLOCK + warp;

    __shared__ __align__(16) float s_exp[WARPS_PER_BLOCK][NC]; // per-warp exp row
    __shared__ float s_tc[NT], s_tw[NT];   // target center/width (unscaled)
    __shared__ float s_ts[NT], s_te[NT];   // target start/end (scaled by L)
    __shared__ int   s_lab[NT];

    const float L = lengths[b];

    // Warp 0: detect label dtype (probe batch 0: indices < 66, in-bounds for
    // both int32 (2048 elems) and int64 (4096 int-words) layouts), then load
    // this batch's targets.
    if (threadIdx.x < NT) {
        const int t  = threadIdx.x;
        // int64 little-endian: element t = words {2t lo, 2t+1 hi}; labels in
        // [0,200) so hi must be 0. Genuine int32 random labels can't have all
        // 32 odd words zero AND all even words in range.
        const int lo = labels32[2 * t];
        const int hi = labels32[2 * t + 1];
        const bool ok64 = (hi == 0) && ((unsigned)lo < (unsigned)NC);
        const unsigned m = __ballot_sync(0xffffffffu, ok64);
        const bool is64 = (m == 0xffffffffu);

        const int idx = b * NT + t;
        s_lab[t] = is64 ? labels32[2 * idx] : labels32[idx];

        const float c = tgt_seg[(size_t)idx * 2 + 0];
        const float w = tgt_seg[(size_t)idx * 2 + 1];
        s_tc[t] = c;
        s_tw[t] = w;
        const float cs = c * L;
        const float ws = w * L;
        s_ts[t] = cs - 0.5f * ws;
        s_te[t] = cs + 0.5f * ws;
    }
    __syncthreads();

    if (q >= NQ) return;

    // ---- softmax denominator over 200 classes (one warp per row) ----
    // Row is 800 bytes, 16B-aligned: 50 float4 loads (LDG.128, coalesced).
    const float4* __restrict__ row4 =
        (const float4*)(logits + ((size_t)b * NQ + q) * NC);
    float4* __restrict__ s_exp4 = (float4*)s_exp[warp];

    float sum = 0.0f;
    #pragma unroll
    for (int v = lane; v < NC4; v += 32) {
        const float4 f = row4[v];
        float4 e;
        e.x = __expf(f.x);
        e.y = __expf(f.y);
        e.z = __expf(f.z);
        e.w = __expf(f.w);
        s_exp4[v] = e;                       // STS.128, conflict-free
        sum += (e.x + e.y) + (e.z + e.w);
    }
    #pragma unroll
    for (int off = 16; off; off >>= 1)
        sum += __shfl_xor_sync(0xffffffffu, sum, off);
    const float inv_sum = 1.0f / sum;

    __syncwarp();  // s_exp visible across the warp before the label gather

    // ---- this query's segment ----
    const float cq = pred_seg[((size_t)b * NQ + q) * 2 + 0];
    const float wq = pred_seg[((size_t)b * NQ + q) * 2 + 1];
    const float cqs = cq * L;
    const float wqs = wq * L;
    const float s1 = cqs - 0.5f * wqs;
    const float e1 = cqs + 0.5f * wqs;
    const float len1 = e1 - s1;

    // ---- lane t handles target t (NT == 32) ----
    const int t = lane;
    const float cost_class = -s_exp[warp][s_lab[t]] * inv_sum;

    const float cost_seg = fabsf(cq - s_tc[t]) + fabsf(wq - s_tw[t]);

    const float s2 = s_ts[t];
    const float e2 = s_te[t];
    float inter = fminf(e1, e2) - fmaxf(s1, s2);
    inter = fmaxf(inter, 0.0f);
    const float uni = len1 + (e2 - s2) - inter;
    const float iou = inter / uni;
    const float enc = fmaxf(e1, e2) - fminf(s1, s2);
    const float giou = iou - (enc - uni) / enc;

    out[((size_t)b * NQ + q) * NT + t] = cost_seg + cost_class - giou;
}

extern "C" void kernel_launch(void* const* d_in, const int* in_sizes, int n_in,
                              void* d_out, int out_size)
{
    const float* logits   = (const float*)d_in[0];
    const float* pred_seg = (const float*)d_in[1];
    const float* tgt_seg  = (const float*)d_in[2];
    const float* lengths  = (const float*)d_in[3];
    const int*   labels   = (const int*)d_in[4];
    float*       out      = (float*)d_out;

    dim3 grid((NQ + WARPS_PER_BLOCK - 1) / WARPS_PER_BLOCK, BS);
    dim3 block(WARPS_PER_BLOCK * 32);
    matcher_kernel<<<grid, block>>>(logits, pred_seg, tgt_seg, lengths,
                                    labels, out);
}